// round 6
// baseline (speedup 1.0000x reference)
#include <cuda_runtime.h>
#include <math.h>
#include <stdint.h>

// Problem constants (fixed by the dataset)
#define NN   100000
#define EE   1600000
#define ETOT (EE + NN)          // edges + self loops
#define F1   128                // input features
#define F2   256                // HEADS*HID
#define NEG_SLOPE 0.2f

// ---------------- scratch (device globals; no allocations allowed) ----------
__device__ float g_aggx[(size_t)NN * 512]; // per-head weighted sum of x  [N,4,128]
__device__ float g_h2[(size_t)NN * F2];    // elu(agg1 @ W1 + b1)        [N,256]
__device__ float g_ws[F1 * 4];             // W1_h @ a_src1[h]           [128,4]
__device__ float g_wd[F1 * 4];
__device__ float g_as1[NN * 4];
__device__ float g_ad1[NN * 4];
__device__ float g_h3[NN * 2];
__device__ float g_as2[NN];
__device__ float g_ad2[NN];
__device__ int   g_cnt[NN];
__device__ int   g_rowptr[NN + 1];
__device__ int   g_cursor[NN];
__device__ int   g_csr[ETOT];              // src node per incoming edge, grouped by dst

__device__ __forceinline__ float lrelu(float x) { return x > 0.f ? x : NEG_SLOPE * x; }
__device__ __forceinline__ float elu1(float x)  { return x > 0.f ? x : expm1f(x); }

// ---------------- CSR construction ------------------------------------------
__global__ void k_init_cnt() {
    int i = blockIdx.x * blockDim.x + threadIdx.x;
    if (i < NN) g_cnt[i] = 1;   // self loop
}

__global__ void k_degree(const int* __restrict__ ei) {
    int i = blockIdx.x * blockDim.x + threadIdx.x;
    if (i < EE) atomicAdd(&g_cnt[ei[EE + i]], 1);
}

// single-block exclusive scan over g_cnt -> g_rowptr / g_cursor
__global__ void k_scan() {
    __shared__ int part[1024];
    int tid = threadIdx.x;
    const int chunk = (NN + 1023) / 1024;
    int start = tid * chunk;
    int end   = min(start + chunk, NN);
    int sum = 0;
    for (int i = start; i < end; i++) sum += g_cnt[i];
    part[tid] = sum;
    __syncthreads();
    for (int off = 1; off < 1024; off <<= 1) {
        int v = 0;
        if (tid >= off) v = part[tid - off];
        __syncthreads();
        if (tid >= off) part[tid] += v;
        __syncthreads();
    }
    int run = (tid == 0) ? 0 : part[tid - 1];
    for (int i = start; i < end; i++) {
        g_rowptr[i] = run;
        g_cursor[i] = run;
        run += g_cnt[i];
    }
    if (tid == 1023) g_rowptr[NN] = part[1023];
}

__global__ void k_scatter(const int* __restrict__ ei) {
    int i = blockIdx.x * blockDim.x + threadIdx.x;
    if (i < EE) {
        int s = ei[i];
        int d = ei[EE + i];
        int p = atomicAdd(&g_cursor[d], 1);
        g_csr[p] = s;
    } else if (i < ETOT) {
        int n = i - EE;
        int p = atomicAdd(&g_cursor[n], 1);
        g_csr[p] = n;   // self loop
    }
}

// ---------------- fold attention vectors through W1:  ws = W1_h @ a_src[h] --
__global__ void k_wvec(const float* __restrict__ W1,
                       const float* __restrict__ aS1,
                       const float* __restrict__ aD1) {
    int t = blockIdx.x * blockDim.x + threadIdx.x;   // 512 outputs
    if (t >= F1 * 4) return;
    int f = t >> 2, h = t & 3;
    const float* wrow = W1 + (size_t)f * F2 + h * 64;
    const float* as = aS1 + h * 64;
    const float* ad = aD1 + h * 64;
    float ss = 0.f, sd = 0.f;
    #pragma unroll
    for (int c = 0; c < 64; c++) {
        float w = wrow[c];
        ss += w * as[c];
        sd += w * ad[c];
    }
    g_ws[f * 4 + h] = ss;
    g_wd[f * 4 + h] = sd;
}

// ---------------- alpha_src / alpha_dst from x (warp per node) --------------
__global__ __launch_bounds__(256) void k_alphax(const float* __restrict__ x) {
    int n = (blockIdx.x * blockDim.x + threadIdx.x) >> 5;
    int lane = threadIdx.x & 31;
    if (n >= NN) return;
    const float4* ws4 = (const float4*)g_ws;   // [128] float4 (per-feature, 4 heads)
    const float4* wd4 = (const float4*)g_wd;
    float4 x4 = ((const float4*)x)[(size_t)n * 32 + lane];

    float4 aS = make_float4(0, 0, 0, 0), aD = make_float4(0, 0, 0, 0);
    #pragma unroll
    for (int j = 0; j < 4; j++) {
        float xv = (&x4.x)[j];
        float4 w = ws4[4 * lane + j];
        aS.x += xv * w.x; aS.y += xv * w.y; aS.z += xv * w.z; aS.w += xv * w.w;
        float4 v = wd4[4 * lane + j];
        aD.x += xv * v.x; aD.y += xv * v.y; aD.z += xv * v.z; aD.w += xv * v.w;
    }
    #pragma unroll
    for (int o = 16; o; o >>= 1) {
        aS.x += __shfl_xor_sync(0xffffffffu, aS.x, o);
        aS.y += __shfl_xor_sync(0xffffffffu, aS.y, o);
        aS.z += __shfl_xor_sync(0xffffffffu, aS.z, o);
        aS.w += __shfl_xor_sync(0xffffffffu, aS.w, o);
        aD.x += __shfl_xor_sync(0xffffffffu, aD.x, o);
        aD.y += __shfl_xor_sync(0xffffffffu, aD.y, o);
        aD.z += __shfl_xor_sync(0xffffffffu, aD.z, o);
        aD.w += __shfl_xor_sync(0xffffffffu, aD.w, o);
    }
    if (lane == 0) {
        *(float4*)(g_as1 + 4 * n) = aS;
        *(float4*)(g_ad1 + 4 * n) = aD;
    }
}

// ---------------- layer-1 softmax + weighted-x aggregation (warp per dst) ---
__global__ __launch_bounds__(256) void k_agg1x(const float* __restrict__ x) {
    int n = (blockIdx.x * blockDim.x + threadIdx.x) >> 5;
    int lane = threadIdx.x & 31;
    if (n >= NN) return;
    int beg = g_rowptr[n], end = g_rowptr[n + 1];
    float4 ad = *(const float4*)(g_ad1 + 4 * n);

    // pass 1: per-head max (lanes parallel over edges)
    float m0 = -1e30f, m1 = -1e30f, m2 = -1e30f, m3 = -1e30f;
    for (int e = beg + lane; e < end; e += 32) {
        int s = g_csr[e];
        float4 as = *(const float4*)(g_as1 + 4 * s);
        m0 = fmaxf(m0, lrelu(as.x + ad.x));
        m1 = fmaxf(m1, lrelu(as.y + ad.y));
        m2 = fmaxf(m2, lrelu(as.z + ad.z));
        m3 = fmaxf(m3, lrelu(as.w + ad.w));
    }
    #pragma unroll
    for (int o = 16; o; o >>= 1) {
        m0 = fmaxf(m0, __shfl_xor_sync(0xffffffffu, m0, o));
        m1 = fmaxf(m1, __shfl_xor_sync(0xffffffffu, m1, o));
        m2 = fmaxf(m2, __shfl_xor_sync(0xffffffffu, m2, o));
        m3 = fmaxf(m3, __shfl_xor_sync(0xffffffffu, m3, o));
    }

    // pass 2: per-head sum of exp(e - m)
    float s0 = 0, s1 = 0, s2 = 0, s3 = 0;
    for (int e = beg + lane; e < end; e += 32) {
        int s = g_csr[e];
        float4 as = *(const float4*)(g_as1 + 4 * s);
        s0 += __expf(lrelu(as.x + ad.x) - m0);
        s1 += __expf(lrelu(as.y + ad.y) - m1);
        s2 += __expf(lrelu(as.z + ad.z) - m2);
        s3 += __expf(lrelu(as.w + ad.w) - m3);
    }
    #pragma unroll
    for (int o = 16; o; o >>= 1) {
        s0 += __shfl_xor_sync(0xffffffffu, s0, o);
        s1 += __shfl_xor_sync(0xffffffffu, s1, o);
        s2 += __shfl_xor_sync(0xffffffffu, s2, o);
        s3 += __shfl_xor_sync(0xffffffffu, s3, o);
    }
    float r0 = 1.f / s0, r1 = 1.f / s1, r2 = 1.f / s2, r3 = 1.f / s3;

    // pass 3: edges serial; lanes span 128 features of x (1 float4 per lane);
    // accumulate 4 per-head weighted sums.
    float4 a0 = {0, 0, 0, 0}, a1 = {0, 0, 0, 0}, a2 = {0, 0, 0, 0}, a3 = {0, 0, 0, 0};
    const float4* xv = (const float4*)x;
    #pragma unroll 2
    for (int e = beg; e < end; e++) {
        int s = g_csr[e];
        float4 as = *(const float4*)(g_as1 + 4 * s);
        float w0 = __expf(lrelu(as.x + ad.x) - m0) * r0;
        float w1 = __expf(lrelu(as.y + ad.y) - m1) * r1;
        float w2 = __expf(lrelu(as.z + ad.z) - m2) * r2;
        float w3 = __expf(lrelu(as.w + ad.w) - m3) * r3;
        float4 v = xv[(size_t)s * 32 + lane];
        a0.x += v.x * w0; a0.y += v.y * w0; a0.z += v.z * w0; a0.w += v.w * w0;
        a1.x += v.x * w1; a1.y += v.y * w1; a1.z += v.z * w1; a1.w += v.w * w1;
        a2.x += v.x * w2; a2.y += v.y * w2; a2.z += v.z * w2; a2.w += v.w * w2;
        a3.x += v.x * w3; a3.y += v.y * w3; a3.z += v.z * w3; a3.w += v.w * w3;
    }
    float4* og = (float4*)g_aggx + (size_t)n * 128 + lane;
    og[0]  = a0;
    og[32] = a1;
    og[64] = a2;
    og[96] = a3;
}

// ---------------- GEMM post-agg (tf32x3): h2 = elu(aggx_h @ W1_h + b1) ------
#define GBM 128
#define GBN 64
#define GBK 32
#define ASTRIDE 36
#define BSTRIDE 72

__device__ __forceinline__ uint32_t f2tf32(float f) {
    uint32_t r;
    asm("cvt.rna.tf32.f32 %0, %1;" : "=r"(r) : "f"(f));
    return r;
}
__device__ __forceinline__ void split_tf32(float f, uint32_t& hi, uint32_t& lo) {
    hi = f2tf32(f);
    lo = f2tf32(f - __uint_as_float(hi));
}
__device__ __forceinline__ void mma_tf32(float* c, uint32_t a0, uint32_t a1,
                                         uint32_t a2, uint32_t a3,
                                         uint32_t b0, uint32_t b1) {
    asm volatile(
        "mma.sync.aligned.m16n8k8.row.col.f32.tf32.tf32.f32 "
        "{%0,%1,%2,%3}, {%4,%5,%6,%7}, {%8,%9}, {%0,%1,%2,%3};"
        : "+f"(c[0]), "+f"(c[1]), "+f"(c[2]), "+f"(c[3])
        : "r"(a0), "r"(a1), "r"(a2), "r"(a3), "r"(b0), "r"(b1));
}

__global__ __launch_bounds__(256) void k_gemm_post(const float* __restrict__ B,
                                                   const float* __restrict__ b1) {
    __shared__ float As[GBM * ASTRIDE];
    __shared__ float Bs[GBK * BSTRIDE];
    const int tid  = threadIdx.x;
    const int wid  = tid >> 5;
    const int lane = tid & 31;
    const int grp  = lane >> 2;
    const int tig  = lane & 3;
    const int wm   = wid & 1;
    const int wn   = wid >> 1;
    const int m0   = blockIdx.x * GBM;
    const int head = blockIdx.y;
    const float* A = g_aggx + (size_t)head * 128;   // row stride 512

    float acc[4][2][4];
    #pragma unroll
    for (int i = 0; i < 4; i++)
        #pragma unroll
        for (int j = 0; j < 2; j++)
            #pragma unroll
            for (int k = 0; k < 4; k++) acc[i][j][k] = 0.f;

    float4 pa[4], pb[2];
    auto loadA = [&](int k0, float4* r) {
        #pragma unroll
        for (int i = 0; i < 4; i++) {
            int f = tid + i * 256;
            int row = f >> 3, c4 = f & 7;
            int gr = m0 + row;
            r[i] = (gr < NN) ? *(const float4*)(A + (size_t)gr * 512 + k0 + 4 * c4)
                             : make_float4(0.f, 0.f, 0.f, 0.f);
        }
    };
    auto loadB = [&](int k0, float4* r) {
        #pragma unroll
        for (int i = 0; i < 2; i++) {
            int f = tid + i * 256;
            int row = f >> 4, c4 = f & 15;
            r[i] = *(const float4*)(B + (size_t)(k0 + row) * F2 + head * 64 + 4 * c4);
        }
    };

    loadA(0, pa);
    loadB(0, pb);

    for (int k0 = 0; k0 < F1; k0 += GBK) {
        #pragma unroll
        for (int i = 0; i < 4; i++) {
            int f = tid + i * 256;
            int row = f >> 3, c4 = f & 7;
            *(float4*)(As + row * ASTRIDE + 4 * c4) = pa[i];
        }
        #pragma unroll
        for (int i = 0; i < 2; i++) {
            int f = tid + i * 256;
            int row = f >> 4, c4 = f & 15;
            *(float4*)(Bs + row * BSTRIDE + 4 * c4) = pb[i];
        }
        __syncthreads();

        if (k0 + GBK < F1) {
            loadA(k0 + GBK, pa);
            loadB(k0 + GBK, pb);
        }

        #pragma unroll
        for (int ks = 0; ks < GBK / 8; ks++) {
            const int kb = ks * 8;
            uint32_t ahi[4][4], alo[4][4];
            #pragma unroll
            for (int mt = 0; mt < 4; mt++) {
                int r = wm * 64 + mt * 16 + grp;
                float v0 = As[r * ASTRIDE + kb + tig];
                float v1 = As[(r + 8) * ASTRIDE + kb + tig];
                float v2 = As[r * ASTRIDE + kb + tig + 4];
                float v3 = As[(r + 8) * ASTRIDE + kb + tig + 4];
                split_tf32(v0, ahi[mt][0], alo[mt][0]);
                split_tf32(v1, ahi[mt][1], alo[mt][1]);
                split_tf32(v2, ahi[mt][2], alo[mt][2]);
                split_tf32(v3, ahi[mt][3], alo[mt][3]);
            }
            uint32_t bhi[2][2], blo[2][2];
            #pragma unroll
            for (int nt = 0; nt < 2; nt++) {
                int c = wn * 16 + nt * 8 + grp;
                float v0 = Bs[(kb + tig) * BSTRIDE + c];
                float v1 = Bs[(kb + tig + 4) * BSTRIDE + c];
                split_tf32(v0, bhi[nt][0], blo[nt][0]);
                split_tf32(v1, bhi[nt][1], blo[nt][1]);
            }
            #pragma unroll
            for (int mt = 0; mt < 4; mt++) {
                #pragma unroll
                for (int nt = 0; nt < 2; nt++) {
                    float* c = acc[mt][nt];
                    mma_tf32(c, ahi[mt][0], ahi[mt][1], ahi[mt][2], ahi[mt][3],
                             bhi[nt][0], bhi[nt][1]);
                    mma_tf32(c, ahi[mt][0], ahi[mt][1], ahi[mt][2], ahi[mt][3],
                             blo[nt][0], blo[nt][1]);
                    mma_tf32(c, alo[mt][0], alo[mt][1], alo[mt][2], alo[mt][3],
                             bhi[nt][0], bhi[nt][1]);
                }
            }
        }
        __syncthreads();
    }

    #pragma unroll
    for (int mt = 0; mt < 4; mt++) {
        int r = m0 + wm * 64 + mt * 16 + grp;
        #pragma unroll
        for (int nt = 0; nt < 2; nt++) {
            int c = head * 64 + wn * 16 + nt * 8 + 2 * tig;
            float bb0 = b1[c], bb1 = b1[c + 1];
            if (r < NN)
                *(float2*)(g_h2 + (size_t)r * F2 + c) =
                    make_float2(elu1(acc[mt][nt][0] + bb0), elu1(acc[mt][nt][1] + bb1));
            if (r + 8 < NN)
                *(float2*)(g_h2 + (size_t)(r + 8) * F2 + c) =
                    make_float2(elu1(acc[mt][nt][2] + bb0), elu1(acc[mt][nt][3] + bb1));
        }
    }
}

// ---------------- layer-2 linear (256 -> 2) + alphas (warp per node) --------
__global__ __launch_bounds__(256) void k_gemm2(const float* __restrict__ W2,
                                               const float* __restrict__ aS,
                                               const float* __restrict__ aD) {
    int n = (blockIdx.x * blockDim.x + threadIdx.x) >> 5;
    int lane = threadIdx.x & 31;
    if (n >= NN) return;
    float s0 = 0, s1 = 0;
    #pragma unroll
    for (int k = 0; k < 8; k++) {
        int f = lane + 32 * k;
        float v = g_h2[(size_t)n * F2 + f];
        float2 w = *(const float2*)(W2 + 2 * f);
        s0 += v * w.x;
        s1 += v * w.y;
    }
    #pragma unroll
    for (int o = 16; o; o >>= 1) {
        s0 += __shfl_xor_sync(0xffffffffu, s0, o);
        s1 += __shfl_xor_sync(0xffffffffu, s1, o);
    }
    if (lane == 0) {
        g_h3[2 * n] = s0;
        g_h3[2 * n + 1] = s1;
        g_as2[n] = s0 * aS[0] + s1 * aS[1];
        g_ad2[n] = s0 * aD[0] + s1 * aD[1];
    }
}

// ---------------- layer-2 softmax + aggregation (warp per dst node) --------
__global__ __launch_bounds__(256) void k_agg2(float* __restrict__ out,
                                              const float* __restrict__ b2) {
    int n = (blockIdx.x * blockDim.x + threadIdx.x) >> 5;
    int lane = threadIdx.x & 31;
    if (n >= NN) return;
    int beg = g_rowptr[n], end = g_rowptr[n + 1];
    float adv = g_ad2[n];

    float m = -1e30f;
    for (int e = beg + lane; e < end; e += 32)
        m = fmaxf(m, lrelu(g_as2[g_csr[e]] + adv));
    #pragma unroll
    for (int o = 16; o; o >>= 1)
        m = fmaxf(m, __shfl_xor_sync(0xffffffffu, m, o));

    float s = 0, p0 = 0, p1 = 0;
    for (int e = beg + lane; e < end; e += 32) {
        int sn = g_csr[e];
        float ex = __expf(lrelu(g_as2[sn] + adv) - m);
        float2 h = *(const float2*)(g_h3 + 2 * sn);
        s += ex;
        p0 += ex * h.x;
        p1 += ex * h.y;
    }
    #pragma unroll
    for (int o = 16; o; o >>= 1) {
        s  += __shfl_xor_sync(0xffffffffu, s, o);
        p0 += __shfl_xor_sync(0xffffffffu, p0, o);
        p1 += __shfl_xor_sync(0xffffffffu, p1, o);
    }
    if (lane == 0) {
        float inv = 1.f / s;
        out[2 * n]     = p0 * inv + b2[0];
        out[2 * n + 1] = p1 * inv + b2[1];
    }
}

// ---------------- launch ----------------------------------------------------
extern "C" void kernel_launch(void* const* d_in, const int* in_sizes, int n_in,
                              void* d_out, int out_size) {
    const float* x   = (const float*)d_in[0];
    const int*   ei  = (const int*)  d_in[1];
    const float* W1  = (const float*)d_in[2];
    const float* aS1 = (const float*)d_in[3];
    const float* aD1 = (const float*)d_in[4];
    const float* b1  = (const float*)d_in[5];
    const float* W2  = (const float*)d_in[6];
    const float* aS2 = (const float*)d_in[7];
    const float* aD2 = (const float*)d_in[8];
    const float* b2  = (const float*)d_in[9];
    float* out = (float*)d_out;

    // CSR build (graph identical across both layers)
    k_init_cnt<<<(NN + 255) / 256, 256>>>();
    k_degree<<<(EE + 255) / 256, 256>>>(ei);
    k_scan<<<1, 1024>>>();
    k_scatter<<<(ETOT + 255) / 256, 256>>>(ei);

    // fold attention vectors through W1, then alphas straight from x
    k_wvec<<<2, 256>>>(W1, aS1, aD1);
    int warpGrid = (NN * 32 + 255) / 256;
    k_alphax<<<warpGrid, 256>>>(x);

    // layer 1: aggregate x with softmax weights, then one GEMM per head
    k_agg1x<<<warpGrid, 256>>>(x);
    k_gemm_post<<<dim3((NN + GBM - 1) / GBM, 4), 256>>>(W1, b1);

    // layer 2
    k_gemm2<<<warpGrid, 256>>>(W2, aS2, aD2);
    k_agg2<<<warpGrid, 256>>>(out, b2);
}

// round 7
// speedup vs baseline: 1.0670x; 1.0670x over previous
#include <cuda_runtime.h>
#include <math.h>
#include <stdint.h>

// Problem constants (fixed by the dataset)
#define NN   100000
#define EE   1600000
#define ETOT (EE + NN)          // edges + self loops
#define F1   128                // input features
#define F2   256                // HEADS*HID
#define NEG_SLOPE 0.2f

// ---------------- scratch (device globals; no allocations allowed) ----------
__device__ float g_h1[(size_t)NN * F2];   // layer1 linear output  [N,256]
__device__ float g_h2[(size_t)NN * F2];   // elu(agg1 + b1)        [N,256]
__device__ float g_ws[F1 * 4];            // W1_h @ a_src1[h]      [128,4]
__device__ float g_wd[F1 * 4];
__device__ float g_as1[NN * 4];
__device__ float g_ad1[NN * 4];
__device__ float g_h3[NN * 2];
__device__ float g_as2[NN];
__device__ float g_ad2[NN];
__device__ int   g_cnt[NN];
__device__ int   g_rowptr[NN + 1];
__device__ int   g_cursor[NN];
__device__ int   g_csr[ETOT];             // src node per incoming edge, grouped by dst

__device__ __forceinline__ float lrelu(float x) { return x > 0.f ? x : NEG_SLOPE * x; }
__device__ __forceinline__ float elu1(float x)  { return x > 0.f ? x : expm1f(x); }

// ---------------- CSR construction ------------------------------------------
__global__ void k_init_cnt() {
    int i = blockIdx.x * blockDim.x + threadIdx.x;
    if (i < NN) g_cnt[i] = 1;   // self loop
}

__global__ void k_degree(const int* __restrict__ ei) {
    int i = blockIdx.x * blockDim.x + threadIdx.x;
    if (i < EE) atomicAdd(&g_cnt[ei[EE + i]], 1);
}

// single-block exclusive scan over g_cnt -> g_rowptr / g_cursor
__global__ void k_scan() {
    __shared__ int part[1024];
    int tid = threadIdx.x;
    const int chunk = (NN + 1023) / 1024;
    int start = tid * chunk;
    int end   = min(start + chunk, NN);
    int sum = 0;
    for (int i = start; i < end; i++) sum += g_cnt[i];
    part[tid] = sum;
    __syncthreads();
    for (int off = 1; off < 1024; off <<= 1) {
        int v = 0;
        if (tid >= off) v = part[tid - off];
        __syncthreads();
        if (tid >= off) part[tid] += v;
        __syncthreads();
    }
    int run = (tid == 0) ? 0 : part[tid - 1];
    for (int i = start; i < end; i++) {
        g_rowptr[i] = run;
        g_cursor[i] = run;
        run += g_cnt[i];
    }
    if (tid == 1023) g_rowptr[NN] = part[1023];
}

__global__ void k_scatter(const int* __restrict__ ei) {
    int i = blockIdx.x * blockDim.x + threadIdx.x;
    if (i < EE) {
        int s = ei[i];
        int d = ei[EE + i];
        int p = atomicAdd(&g_cursor[d], 1);
        g_csr[p] = s;
    } else if (i < ETOT) {
        int n = i - EE;
        int p = atomicAdd(&g_cursor[n], 1);
        g_csr[p] = n;   // self loop
    }
}

// ---------------- fold attention vectors through W1:  ws = W1_h @ a_src[h] --
__global__ void k_wvec(const float* __restrict__ W1,
                       const float* __restrict__ aS1,
                       const float* __restrict__ aD1) {
    int t = blockIdx.x * blockDim.x + threadIdx.x;   // 512 outputs
    if (t >= F1 * 4) return;
    int f = t >> 2, h = t & 3;
    const float* wrow = W1 + (size_t)f * F2 + h * 64;
    const float* as = aS1 + h * 64;
    const float* ad = aD1 + h * 64;
    float ss = 0.f, sd = 0.f;
    #pragma unroll
    for (int c = 0; c < 64; c++) {
        float w = wrow[c];
        ss += w * as[c];
        sd += w * ad[c];
    }
    g_ws[f * 4 + h] = ss;
    g_wd[f * 4 + h] = sd;
}

// ---------------- alpha_src / alpha_dst from x (warp per node) --------------
__global__ __launch_bounds__(256) void k_alphax(const float* __restrict__ x) {
    int n = (blockIdx.x * blockDim.x + threadIdx.x) >> 5;
    int lane = threadIdx.x & 31;
    if (n >= NN) return;
    const float4* ws4 = (const float4*)g_ws;   // per-feature, 4 heads
    const float4* wd4 = (const float4*)g_wd;
    float4 x4 = ((const float4*)x)[(size_t)n * 32 + lane];

    float4 aS = make_float4(0, 0, 0, 0), aD = make_float4(0, 0, 0, 0);
    #pragma unroll
    for (int j = 0; j < 4; j++) {
        float xv = (&x4.x)[j];
        float4 w = ws4[4 * lane + j];
        aS.x += xv * w.x; aS.y += xv * w.y; aS.z += xv * w.z; aS.w += xv * w.w;
        float4 v = wd4[4 * lane + j];
        aD.x += xv * v.x; aD.y += xv * v.y; aD.z += xv * v.z; aD.w += xv * v.w;
    }
    #pragma unroll
    for (int o = 16; o; o >>= 1) {
        aS.x += __shfl_xor_sync(0xffffffffu, aS.x, o);
        aS.y += __shfl_xor_sync(0xffffffffu, aS.y, o);
        aS.z += __shfl_xor_sync(0xffffffffu, aS.z, o);
        aS.w += __shfl_xor_sync(0xffffffffu, aS.w, o);
        aD.x += __shfl_xor_sync(0xffffffffu, aD.x, o);
        aD.y += __shfl_xor_sync(0xffffffffu, aD.y, o);
        aD.z += __shfl_xor_sync(0xffffffffu, aD.z, o);
        aD.w += __shfl_xor_sync(0xffffffffu, aD.w, o);
    }
    if (lane == 0) {
        *(float4*)(g_as1 + 4 * n) = aS;
        *(float4*)(g_ad1 + 4 * n) = aD;
    }
}

// ---------------- GEMM1 (tensor cores, tf32x3): h1 = x @ W1 -----------------
#define GBM 128
#define GBN 64
#define GBK 32
#define ASTRIDE 36
#define BSTRIDE 72

__device__ __forceinline__ uint32_t f2tf32(float f) {
    uint32_t r;
    asm("cvt.rna.tf32.f32 %0, %1;" : "=r"(r) : "f"(f));
    return r;
}
__device__ __forceinline__ void split_tf32(float f, uint32_t& hi, uint32_t& lo) {
    hi = f2tf32(f);
    lo = f2tf32(f - __uint_as_float(hi));
}
__device__ __forceinline__ void mma_tf32(float* c, uint32_t a0, uint32_t a1,
                                         uint32_t a2, uint32_t a3,
                                         uint32_t b0, uint32_t b1) {
    asm volatile(
        "mma.sync.aligned.m16n8k8.row.col.f32.tf32.tf32.f32 "
        "{%0,%1,%2,%3}, {%4,%5,%6,%7}, {%8,%9}, {%0,%1,%2,%3};"
        : "+f"(c[0]), "+f"(c[1]), "+f"(c[2]), "+f"(c[3])
        : "r"(a0), "r"(a1), "r"(a2), "r"(a3), "r"(b0), "r"(b1));
}

__global__ __launch_bounds__(256) void k_gemm1_tc(const float* __restrict__ A,
                                                  const float* __restrict__ B) {
    __shared__ float As[GBM * ASTRIDE];
    __shared__ float Bs[GBK * BSTRIDE];
    const int tid  = threadIdx.x;
    const int wid  = tid >> 5;
    const int lane = tid & 31;
    const int grp  = lane >> 2;
    const int tig  = lane & 3;
    const int wm   = wid & 1;
    const int wn   = wid >> 1;
    const int m0   = blockIdx.x * GBM;
    const int n0   = blockIdx.y * GBN;

    float acc[4][2][4];
    #pragma unroll
    for (int i = 0; i < 4; i++)
        #pragma unroll
        for (int j = 0; j < 2; j++)
            #pragma unroll
            for (int k = 0; k < 4; k++) acc[i][j][k] = 0.f;

    float4 pa[4], pb[2];
    auto loadA = [&](int k0, float4* r) {
        #pragma unroll
        for (int i = 0; i < 4; i++) {
            int f = tid + i * 256;
            int row = f >> 3, c4 = f & 7;
            int gr = m0 + row;
            r[i] = (gr < NN) ? *(const float4*)(A + (size_t)gr * F1 + k0 + 4 * c4)
                             : make_float4(0.f, 0.f, 0.f, 0.f);
        }
    };
    auto loadB = [&](int k0, float4* r) {
        #pragma unroll
        for (int i = 0; i < 2; i++) {
            int f = tid + i * 256;
            int row = f >> 4, c4 = f & 15;
            r[i] = *(const float4*)(B + (size_t)(k0 + row) * F2 + n0 + 4 * c4);
        }
    };

    loadA(0, pa);
    loadB(0, pb);

    for (int k0 = 0; k0 < F1; k0 += GBK) {
        #pragma unroll
        for (int i = 0; i < 4; i++) {
            int f = tid + i * 256;
            int row = f >> 3, c4 = f & 7;
            *(float4*)(As + row * ASTRIDE + 4 * c4) = pa[i];
        }
        #pragma unroll
        for (int i = 0; i < 2; i++) {
            int f = tid + i * 256;
            int row = f >> 4, c4 = f & 15;
            *(float4*)(Bs + row * BSTRIDE + 4 * c4) = pb[i];
        }
        __syncthreads();

        if (k0 + GBK < F1) {
            loadA(k0 + GBK, pa);
            loadB(k0 + GBK, pb);
        }

        #pragma unroll
        for (int ks = 0; ks < GBK / 8; ks++) {
            const int kb = ks * 8;
            uint32_t ahi[4][4], alo[4][4];
            #pragma unroll
            for (int mt = 0; mt < 4; mt++) {
                int r = wm * 64 + mt * 16 + grp;
                float v0 = As[r * ASTRIDE + kb + tig];
                float v1 = As[(r + 8) * ASTRIDE + kb + tig];
                float v2 = As[r * ASTRIDE + kb + tig + 4];
                float v3 = As[(r + 8) * ASTRIDE + kb + tig + 4];
                split_tf32(v0, ahi[mt][0], alo[mt][0]);
                split_tf32(v1, ahi[mt][1], alo[mt][1]);
                split_tf32(v2, ahi[mt][2], alo[mt][2]);
                split_tf32(v3, ahi[mt][3], alo[mt][3]);
            }
            uint32_t bhi[2][2], blo[2][2];
            #pragma unroll
            for (int nt = 0; nt < 2; nt++) {
                int c = wn * 16 + nt * 8 + grp;
                float v0 = Bs[(kb + tig) * BSTRIDE + c];
                float v1 = Bs[(kb + tig + 4) * BSTRIDE + c];
                split_tf32(v0, bhi[nt][0], blo[nt][0]);
                split_tf32(v1, bhi[nt][1], blo[nt][1]);
            }
            #pragma unroll
            for (int mt = 0; mt < 4; mt++) {
                #pragma unroll
                for (int nt = 0; nt < 2; nt++) {
                    float* c = acc[mt][nt];
                    mma_tf32(c, ahi[mt][0], ahi[mt][1], ahi[mt][2], ahi[mt][3],
                             bhi[nt][0], bhi[nt][1]);
                    mma_tf32(c, ahi[mt][0], ahi[mt][1], ahi[mt][2], ahi[mt][3],
                             blo[nt][0], blo[nt][1]);
                    mma_tf32(c, alo[mt][0], alo[mt][1], alo[mt][2], alo[mt][3],
                             bhi[nt][0], bhi[nt][1]);
                }
            }
        }
        __syncthreads();
    }

    #pragma unroll
    for (int mt = 0; mt < 4; mt++) {
        int r = m0 + wm * 64 + mt * 16 + grp;
        #pragma unroll
        for (int nt = 0; nt < 2; nt++) {
            int c = n0 + wn * 16 + nt * 8 + 2 * tig;
            if (r < NN)
                *(float2*)(g_h1 + (size_t)r * F2 + c) =
                    make_float2(acc[mt][nt][0], acc[mt][nt][1]);
            if (r + 8 < NN)
                *(float2*)(g_h1 + (size_t)(r + 8) * F2 + c) =
                    make_float2(acc[mt][nt][2], acc[mt][nt][3]);
        }
    }
}

// ---------------- layer-1 fused softmax+aggregate (warp per dst, ONE pass) --
// attn = exp(e)/sum(exp(e)) -- max subtraction dropped (|e| ~ few, safe in fp32)
__global__ __launch_bounds__(256) void k_agg1f(const float* __restrict__ b1) {
    int n = (blockIdx.x * blockDim.x + threadIdx.x) >> 5;
    int lane = threadIdx.x & 31;
    if (n >= NN) return;
    int beg = g_rowptr[n], end = g_rowptr[n + 1];
    float4 ad = *(const float4*)(g_ad1 + 4 * n);

    // lanes 0-15: first float4 -> head0 (feats 0..63), second -> head2
    // lanes 16-31: head1 / head3
    bool lo = lane < 16;
    float adA = lo ? ad.x : ad.y, adB = lo ? ad.z : ad.w;

    float4 acc0 = {0, 0, 0, 0}, acc1 = {0, 0, 0, 0};
    float sA = 0.f, sB = 0.f;
    const float4* h1v = (const float4*)g_h1;
    #pragma unroll 2
    for (int e = beg; e < end; e++) {
        int s = g_csr[e];
        float4 as = *(const float4*)(g_as1 + 4 * s);
        float wA = __expf(lrelu((lo ? as.x : as.y) + adA));
        float wB = __expf(lrelu((lo ? as.z : as.w) + adB));
        float4 v0 = h1v[(size_t)s * 64 + lane];
        float4 v1 = h1v[(size_t)s * 64 + 32 + lane];
        sA += wA;
        sB += wB;
        acc0.x += v0.x * wA; acc0.y += v0.y * wA; acc0.z += v0.z * wA; acc0.w += v0.w * wA;
        acc1.x += v1.x * wB; acc1.y += v1.y * wB; acc1.z += v1.z * wB; acc1.w += v1.w * wB;
    }
    float rA = 1.f / sA, rB = 1.f / sB;

    const float4* b1v = (const float4*)b1;
    float4 bb0 = b1v[lane], bb1 = b1v[32 + lane];
    float4 o0, o1;
    o0.x = elu1(acc0.x * rA + bb0.x); o0.y = elu1(acc0.y * rA + bb0.y);
    o0.z = elu1(acc0.z * rA + bb0.z); o0.w = elu1(acc0.w * rA + bb0.w);
    o1.x = elu1(acc1.x * rB + bb1.x); o1.y = elu1(acc1.y * rB + bb1.y);
    o1.z = elu1(acc1.z * rB + bb1.z); o1.w = elu1(acc1.w * rB + bb1.w);
    ((float4*)g_h2)[(size_t)n * 64 + lane]      = o0;
    ((float4*)g_h2)[(size_t)n * 64 + 32 + lane] = o1;
}

// ---------------- layer-2 linear (256 -> 2) + alphas (warp per node) --------
__global__ __launch_bounds__(256) void k_gemm2(const float* __restrict__ W2,
                                               const float* __restrict__ aS,
                                               const float* __restrict__ aD) {
    int n = (blockIdx.x * blockDim.x + threadIdx.x) >> 5;
    int lane = threadIdx.x & 31;
    if (n >= NN) return;
    float s0 = 0, s1 = 0;
    #pragma unroll
    for (int k = 0; k < 8; k++) {
        int f = lane + 32 * k;
        float v = g_h2[(size_t)n * F2 + f];
        float2 w = *(const float2*)(W2 + 2 * f);
        s0 += v * w.x;
        s1 += v * w.y;
    }
    #pragma unroll
    for (int o = 16; o; o >>= 1) {
        s0 += __shfl_xor_sync(0xffffffffu, s0, o);
        s1 += __shfl_xor_sync(0xffffffffu, s1, o);
    }
    if (lane == 0) {
        g_h3[2 * n] = s0;
        g_h3[2 * n + 1] = s1;
        g_as2[n] = s0 * aS[0] + s1 * aS[1];
        g_ad2[n] = s0 * aD[0] + s1 * aD[1];
    }
}

// ---------------- layer-2 fused softmax+aggregate (warp per dst, ONE pass) --
__global__ __launch_bounds__(256) void k_agg2f(float* __restrict__ out,
                                               const float* __restrict__ b2) {
    int n = (blockIdx.x * blockDim.x + threadIdx.x) >> 5;
    int lane = threadIdx.x & 31;
    if (n >= NN) return;
    int beg = g_rowptr[n], end = g_rowptr[n + 1];
    float adv = g_ad2[n];

    float s = 0, p0 = 0, p1 = 0;
    for (int e = beg + lane; e < end; e += 32) {
        int sn = g_csr[e];
        float ex = __expf(lrelu(g_as2[sn] + adv));
        float2 h = *(const float2*)(g_h3 + 2 * sn);
        s += ex;
        p0 += ex * h.x;
        p1 += ex * h.y;
    }
    #pragma unroll
    for (int o = 16; o; o >>= 1) {
        s  += __shfl_xor_sync(0xffffffffu, s, o);
        p0 += __shfl_xor_sync(0xffffffffu, p0, o);
        p1 += __shfl_xor_sync(0xffffffffu, p1, o);
    }
    if (lane == 0) {
        float inv = 1.f / s;
        out[2 * n]     = p0 * inv + b2[0];
        out[2 * n + 1] = p1 * inv + b2[1];
    }
}

// ---------------- launch ----------------------------------------------------
extern "C" void kernel_launch(void* const* d_in, const int* in_sizes, int n_in,
                              void* d_out, int out_size) {
    const float* x   = (const float*)d_in[0];
    const int*   ei  = (const int*)  d_in[1];
    const float* W1  = (const float*)d_in[2];
    const float* aS1 = (const float*)d_in[3];
    const float* aD1 = (const float*)d_in[4];
    const float* b1  = (const float*)d_in[5];
    const float* W2  = (const float*)d_in[6];
    const float* aS2 = (const float*)d_in[7];
    const float* aD2 = (const float*)d_in[8];
    const float* b2  = (const float*)d_in[9];
    float* out = (float*)d_out;

    // CSR build (graph identical across both layers)
    k_init_cnt<<<(NN + 255) / 256, 256>>>();
    k_degree<<<(EE + 255) / 256, 256>>>(ei);
    k_scan<<<1, 1024>>>();
    k_scatter<<<(ETOT + 255) / 256, 256>>>(ei);

    // alphas straight from x (folded through W1)
    k_wvec<<<2, 256>>>(W1, aS1, aD1);
    int warpGrid = (NN * 32 + 255) / 256;
    k_alphax<<<warpGrid, 256>>>(x);

    // layer 1
    k_gemm1_tc<<<dim3((NN + GBM - 1) / GBM, F2 / GBN), 256>>>(x, W1);
    k_agg1f<<<warpGrid, 256>>>(b1);

    // layer 2
    k_gemm2<<<warpGrid, 256>>>(W2, aS2, aD2);
    k_agg2f<<<warpGrid, 256>>>(out, b2);
}

// round 8
// speedup vs baseline: 1.2295x; 1.1523x over previous
#include <cuda_runtime.h>
#include <cuda_fp16.h>
#include <math.h>
#include <stdint.h>

// Problem constants (fixed by the dataset)
#define NN   100000
#define EE   1600000
#define ETOT (EE + NN)          // edges + self loops
#define F1   128                // input features
#define F2   256                // HEADS*HID
#define NEG_SLOPE 0.2f

// ---------------- scratch (device globals; no allocations allowed) ----------
__device__ __half g_h1h[(size_t)NN * F2]; // layer1 linear output, fp16 [N,256]
__device__ float g_ws[F1 * 4];            // W1_h @ a_src1[h]  [128,4]
__device__ float g_wd[F1 * 4];
__device__ float g_as1[NN * 4];
__device__ float g_ad1[NN * 4];
__device__ float g_h3[NN * 2];
__device__ float g_as2[NN];
__device__ float g_ad2[NN];
__device__ int   g_cnt[NN];
__device__ int   g_rowptr[NN + 1];
__device__ int   g_cursor[NN];
__device__ int   g_csr[ETOT];             // src node per incoming edge, grouped by dst

__device__ __forceinline__ float lrelu(float x) { return x > 0.f ? x : NEG_SLOPE * x; }
__device__ __forceinline__ float elu1(float x)  { return x > 0.f ? x : expm1f(x); }

// ---------------- CSR construction ------------------------------------------
__global__ void k_init_cnt() {
    int i = blockIdx.x * blockDim.x + threadIdx.x;
    if (i < NN) g_cnt[i] = 1;   // self loop
}

__global__ void k_degree(const int* __restrict__ ei) {
    int i = blockIdx.x * blockDim.x + threadIdx.x;
    if (i < EE) atomicAdd(&g_cnt[ei[EE + i]], 1);
}

// single-block exclusive scan over g_cnt -> g_rowptr / g_cursor
__global__ void k_scan() {
    __shared__ int part[1024];
    int tid = threadIdx.x;
    const int chunk = (NN + 1023) / 1024;
    int start = tid * chunk;
    int end   = min(start + chunk, NN);
    int sum = 0;
    for (int i = start; i < end; i++) sum += g_cnt[i];
    part[tid] = sum;
    __syncthreads();
    for (int off = 1; off < 1024; off <<= 1) {
        int v = 0;
        if (tid >= off) v = part[tid - off];
        __syncthreads();
        if (tid >= off) part[tid] += v;
        __syncthreads();
    }
    int run = (tid == 0) ? 0 : part[tid - 1];
    for (int i = start; i < end; i++) {
        g_rowptr[i] = run;
        g_cursor[i] = run;
        run += g_cnt[i];
    }
    if (tid == 1023) g_rowptr[NN] = part[1023];
}

__global__ void k_scatter(const int* __restrict__ ei) {
    int i = blockIdx.x * blockDim.x + threadIdx.x;
    if (i < EE) {
        int s = ei[i];
        int d = ei[EE + i];
        int p = atomicAdd(&g_cursor[d], 1);
        g_csr[p] = s;
    } else if (i < ETOT) {
        int n = i - EE;
        int p = atomicAdd(&g_cursor[n], 1);
        g_csr[p] = n;   // self loop
    }
}

// ---------------- fold attention vectors through W1:  ws = W1_h @ a_src[h] --
__global__ void k_wvec(const float* __restrict__ W1,
                       const float* __restrict__ aS1,
                       const float* __restrict__ aD1) {
    int t = blockIdx.x * blockDim.x + threadIdx.x;   // 512 outputs
    if (t >= F1 * 4) return;
    int f = t >> 2, h = t & 3;
    const float* wrow = W1 + (size_t)f * F2 + h * 64;
    const float* as = aS1 + h * 64;
    const float* ad = aD1 + h * 64;
    float ss = 0.f, sd = 0.f;
    #pragma unroll
    for (int c = 0; c < 64; c++) {
        float w = wrow[c];
        ss += w * as[c];
        sd += w * ad[c];
    }
    g_ws[f * 4 + h] = ss;
    g_wd[f * 4 + h] = sd;
}

// ---------------- alpha_src / alpha_dst from x (warp per node) --------------
__global__ __launch_bounds__(256) void k_alphax(const float* __restrict__ x) {
    int n = (blockIdx.x * blockDim.x + threadIdx.x) >> 5;
    int lane = threadIdx.x & 31;
    if (n >= NN) return;
    const float4* ws4 = (const float4*)g_ws;   // per-feature, 4 heads
    const float4* wd4 = (const float4*)g_wd;
    float4 x4 = ((const float4*)x)[(size_t)n * 32 + lane];

    float4 aS = make_float4(0, 0, 0, 0), aD = make_float4(0, 0, 0, 0);
    #pragma unroll
    for (int j = 0; j < 4; j++) {
        float xv = (&x4.x)[j];
        float4 w = ws4[4 * lane + j];
        aS.x += xv * w.x; aS.y += xv * w.y; aS.z += xv * w.z; aS.w += xv * w.w;
        float4 v = wd4[4 * lane + j];
        aD.x += xv * v.x; aD.y += xv * v.y; aD.z += xv * v.z; aD.w += xv * v.w;
    }
    #pragma unroll
    for (int o = 16; o; o >>= 1) {
        aS.x += __shfl_xor_sync(0xffffffffu, aS.x, o);
        aS.y += __shfl_xor_sync(0xffffffffu, aS.y, o);
        aS.z += __shfl_xor_sync(0xffffffffu, aS.z, o);
        aS.w += __shfl_xor_sync(0xffffffffu, aS.w, o);
        aD.x += __shfl_xor_sync(0xffffffffu, aD.x, o);
        aD.y += __shfl_xor_sync(0xffffffffu, aD.y, o);
        aD.z += __shfl_xor_sync(0xffffffffu, aD.z, o);
        aD.w += __shfl_xor_sync(0xffffffffu, aD.w, o);
    }
    if (lane == 0) {
        *(float4*)(g_as1 + 4 * n) = aS;
        *(float4*)(g_ad1 + 4 * n) = aD;
    }
}

// ---------------- GEMM1 (tensor cores, tf32x3): h1 = x @ W1, fp16 out -------
#define GBM 128
#define GBN 64
#define GBK 32
#define ASTRIDE 36
#define BSTRIDE 72

__device__ __forceinline__ uint32_t f2tf32(float f) {
    uint32_t r;
    asm("cvt.rna.tf32.f32 %0, %1;" : "=r"(r) : "f"(f));
    return r;
}
__device__ __forceinline__ void split_tf32(float f, uint32_t& hi, uint32_t& lo) {
    hi = f2tf32(f);
    lo = f2tf32(f - __uint_as_float(hi));
}
__device__ __forceinline__ void mma_tf32(float* c, uint32_t a0, uint32_t a1,
                                         uint32_t a2, uint32_t a3,
                                         uint32_t b0, uint32_t b1) {
    asm volatile(
        "mma.sync.aligned.m16n8k8.row.col.f32.tf32.tf32.f32 "
        "{%0,%1,%2,%3}, {%4,%5,%6,%7}, {%8,%9}, {%0,%1,%2,%3};"
        : "+f"(c[0]), "+f"(c[1]), "+f"(c[2]), "+f"(c[3])
        : "r"(a0), "r"(a1), "r"(a2), "r"(a3), "r"(b0), "r"(b1));
}

__global__ __launch_bounds__(256) void k_gemm1_tc(const float* __restrict__ A,
                                                  const float* __restrict__ B) {
    __shared__ float As[GBM * ASTRIDE];
    __shared__ float Bs[GBK * BSTRIDE];
    const int tid  = threadIdx.x;
    const int wid  = tid >> 5;
    const int lane = tid & 31;
    const int grp  = lane >> 2;
    const int tig  = lane & 3;
    const int wm   = wid & 1;
    const int wn   = wid >> 1;
    const int m0   = blockIdx.x * GBM;
    const int n0   = blockIdx.y * GBN;

    float acc[4][2][4];
    #pragma unroll
    for (int i = 0; i < 4; i++)
        #pragma unroll
        for (int j = 0; j < 2; j++)
            #pragma unroll
            for (int k = 0; k < 4; k++) acc[i][j][k] = 0.f;

    float4 pa[4], pb[2];
    auto loadA = [&](int k0, float4* r) {
        #pragma unroll
        for (int i = 0; i < 4; i++) {
            int f = tid + i * 256;
            int row = f >> 3, c4 = f & 7;
            int gr = m0 + row;
            r[i] = (gr < NN) ? *(const float4*)(A + (size_t)gr * F1 + k0 + 4 * c4)
                             : make_float4(0.f, 0.f, 0.f, 0.f);
        }
    };
    auto loadB = [&](int k0, float4* r) {
        #pragma unroll
        for (int i = 0; i < 2; i++) {
            int f = tid + i * 256;
            int row = f >> 4, c4 = f & 15;
            r[i] = *(const float4*)(B + (size_t)(k0 + row) * F2 + n0 + 4 * c4);
        }
    };

    loadA(0, pa);
    loadB(0, pb);

    for (int k0 = 0; k0 < F1; k0 += GBK) {
        #pragma unroll
        for (int i = 0; i < 4; i++) {
            int f = tid + i * 256;
            int row = f >> 3, c4 = f & 7;
            *(float4*)(As + row * ASTRIDE + 4 * c4) = pa[i];
        }
        #pragma unroll
        for (int i = 0; i < 2; i++) {
            int f = tid + i * 256;
            int row = f >> 4, c4 = f & 15;
            *(float4*)(Bs + row * BSTRIDE + 4 * c4) = pb[i];
        }
        __syncthreads();

        if (k0 + GBK < F1) {
            loadA(k0 + GBK, pa);
            loadB(k0 + GBK, pb);
        }

        #pragma unroll
        for (int ks = 0; ks < GBK / 8; ks++) {
            const int kb = ks * 8;
            uint32_t ahi[4][4], alo[4][4];
            #pragma unroll
            for (int mt = 0; mt < 4; mt++) {
                int r = wm * 64 + mt * 16 + grp;
                float v0 = As[r * ASTRIDE + kb + tig];
                float v1 = As[(r + 8) * ASTRIDE + kb + tig];
                float v2 = As[r * ASTRIDE + kb + tig + 4];
                float v3 = As[(r + 8) * ASTRIDE + kb + tig + 4];
                split_tf32(v0, ahi[mt][0], alo[mt][0]);
                split_tf32(v1, ahi[mt][1], alo[mt][1]);
                split_tf32(v2, ahi[mt][2], alo[mt][2]);
                split_tf32(v3, ahi[mt][3], alo[mt][3]);
            }
            uint32_t bhi[2][2], blo[2][2];
            #pragma unroll
            for (int nt = 0; nt < 2; nt++) {
                int c = wn * 16 + nt * 8 + grp;
                float v0 = Bs[(kb + tig) * BSTRIDE + c];
                float v1 = Bs[(kb + tig + 4) * BSTRIDE + c];
                split_tf32(v0, bhi[nt][0], blo[nt][0]);
                split_tf32(v1, bhi[nt][1], blo[nt][1]);
            }
            #pragma unroll
            for (int mt = 0; mt < 4; mt++) {
                #pragma unroll
                for (int nt = 0; nt < 2; nt++) {
                    float* c = acc[mt][nt];
                    mma_tf32(c, ahi[mt][0], ahi[mt][1], ahi[mt][2], ahi[mt][3],
                             bhi[nt][0], bhi[nt][1]);
                    mma_tf32(c, ahi[mt][0], ahi[mt][1], ahi[mt][2], ahi[mt][3],
                             blo[nt][0], blo[nt][1]);
                    mma_tf32(c, alo[mt][0], alo[mt][1], alo[mt][2], alo[mt][3],
                             bhi[nt][0], bhi[nt][1]);
                }
            }
        }
        __syncthreads();
    }

    // epilogue: convert to fp16
    #pragma unroll
    for (int mt = 0; mt < 4; mt++) {
        int r = m0 + wm * 64 + mt * 16 + grp;
        #pragma unroll
        for (int nt = 0; nt < 2; nt++) {
            int c = n0 + wn * 16 + nt * 8 + 2 * tig;
            if (r < NN)
                *(__half2*)(g_h1h + (size_t)r * F2 + c) =
                    __floats2half2_rn(acc[mt][nt][0], acc[mt][nt][1]);
            if (r + 8 < NN)
                *(__half2*)(g_h1h + (size_t)(r + 8) * F2 + c) =
                    __floats2half2_rn(acc[mt][nt][2], acc[mt][nt][3]);
        }
    }
}

// ---------------- layer-1 softmax+aggregate + layer-2 linear (warp per dst) -
// lane owns features 8*lane..8*lane+7 (head = lane>>3). One uint4 (8 halves)
// gather per lane per edge. Epilogue computes h2 in regs, then h3 = h2 @ W2
// and the layer-2 alphas -- no h2 round-trip to DRAM.
__global__ __launch_bounds__(256) void k_agg1f(const float* __restrict__ b1,
                                               const float* __restrict__ W2,
                                               const float* __restrict__ aS2,
                                               const float* __restrict__ aD2) {
    int n = (blockIdx.x * blockDim.x + threadIdx.x) >> 5;
    int lane = threadIdx.x & 31;
    if (n >= NN) return;
    int beg = g_rowptr[n], end = g_rowptr[n + 1];
    const int head = lane >> 3;
    float ad_h = g_ad1[4 * n + head];

    float acc[8] = {0, 0, 0, 0, 0, 0, 0, 0};
    float ssum = 0.f;
    #pragma unroll 2
    for (int e = beg; e < end; e++) {
        int s = g_csr[e];
        float w = __expf(lrelu(g_as1[4 * s + head] + ad_h));
        uint4 hv = *(const uint4*)(g_h1h + (size_t)s * F2 + 8 * lane);
        const __half2* hp = (const __half2*)&hv;
        ssum += w;
        #pragma unroll
        for (int j = 0; j < 4; j++) {
            float2 f = __half22float2(hp[j]);
            acc[2 * j]     += f.x * w;
            acc[2 * j + 1] += f.y * w;
        }
    }
    float r = 1.f / ssum;

    // h2 features for this lane + layer-2 projection (256 -> 2)
    const int fb = 8 * lane;
    float4 bb0 = *(const float4*)(b1 + fb);
    float4 bb1 = *(const float4*)(b1 + fb + 4);
    float s0 = 0.f, s1 = 0.f;
    #pragma unroll
    for (int j = 0; j < 8; j++) {
        float bj = (j < 4) ? (&bb0.x)[j] : (&bb1.x)[j - 4];
        float h2 = elu1(acc[j] * r + bj);
        float2 w2 = *(const float2*)(W2 + 2 * (fb + j));
        s0 += h2 * w2.x;
        s1 += h2 * w2.y;
    }
    #pragma unroll
    for (int o = 16; o; o >>= 1) {
        s0 += __shfl_xor_sync(0xffffffffu, s0, o);
        s1 += __shfl_xor_sync(0xffffffffu, s1, o);
    }
    if (lane == 0) {
        g_h3[2 * n]     = s0;
        g_h3[2 * n + 1] = s1;
        g_as2[n] = s0 * aS2[0] + s1 * aS2[1];
        g_ad2[n] = s0 * aD2[0] + s1 * aD2[1];
    }
}

// ---------------- layer-2 fused softmax+aggregate (warp per dst, ONE pass) --
__global__ __launch_bounds__(256) void k_agg2f(float* __restrict__ out,
                                               const float* __restrict__ b2) {
    int n = (blockIdx.x * blockDim.x + threadIdx.x) >> 5;
    int lane = threadIdx.x & 31;
    if (n >= NN) return;
    int beg = g_rowptr[n], end = g_rowptr[n + 1];
    float adv = g_ad2[n];

    float s = 0, p0 = 0, p1 = 0;
    for (int e = beg + lane; e < end; e += 32) {
        int sn = g_csr[e];
        float ex = __expf(lrelu(g_as2[sn] + adv));
        float2 h = *(const float2*)(g_h3 + 2 * sn);
        s += ex;
        p0 += ex * h.x;
        p1 += ex * h.y;
    }
    #pragma unroll
    for (int o = 16; o; o >>= 1) {
        s  += __shfl_xor_sync(0xffffffffu, s, o);
        p0 += __shfl_xor_sync(0xffffffffu, p0, o);
        p1 += __shfl_xor_sync(0xffffffffu, p1, o);
    }
    if (lane == 0) {
        float inv = 1.f / s;
        out[2 * n]     = p0 * inv + b2[0];
        out[2 * n + 1] = p1 * inv + b2[1];
    }
}

// ---------------- launch ----------------------------------------------------
extern "C" void kernel_launch(void* const* d_in, const int* in_sizes, int n_in,
                              void* d_out, int out_size) {
    const float* x   = (const float*)d_in[0];
    const int*   ei  = (const int*)  d_in[1];
    const float* W1  = (const float*)d_in[2];
    const float* aS1 = (const float*)d_in[3];
    const float* aD1 = (const float*)d_in[4];
    const float* b1  = (const float*)d_in[5];
    const float* W2  = (const float*)d_in[6];
    const float* aS2 = (const float*)d_in[7];
    const float* aD2 = (const float*)d_in[8];
    const float* b2  = (const float*)d_in[9];
    float* out = (float*)d_out;

    // CSR build (graph identical across both layers)
    k_init_cnt<<<(NN + 255) / 256, 256>>>();
    k_degree<<<(EE + 255) / 256, 256>>>(ei);
    k_scan<<<1, 1024>>>();
    k_scatter<<<(ETOT + 255) / 256, 256>>>(ei);

    // alphas straight from x (folded through W1)
    k_wvec<<<2, 256>>>(W1, aS1, aD1);
    int warpGrid = (NN * 32 + 255) / 256;
    k_alphax<<<warpGrid, 256>>>(x);

    // layer 1 GEMM (fp16 output)
    k_gemm1_tc<<<dim3((NN + GBM - 1) / GBM, F2 / GBN), 256>>>(x, W1);

    // layer-1 aggregate fused with layer-2 linear
    k_agg1f<<<warpGrid, 256>>>(b1, W2, aS2, aD2);

    // layer-2 aggregate
    k_agg2f<<<warpGrid, 256>>>(out, b2);
}

// round 9
// speedup vs baseline: 1.6191x; 1.3168x over previous
#include <cuda_runtime.h>
#include <cuda_fp16.h>
#include <math.h>
#include <stdint.h>

// Problem constants (fixed by the dataset)
#define NN   100000
#define EE   1600000
#define ETOT (EE + NN)          // edges + self loops
#define F1   128                // input features
#define F2   256                // HEADS*HID
#define NEG_SLOPE 0.2f

// ---------------- scratch (device globals; no allocations allowed) ----------
__device__ __half g_h1h[(size_t)NN * F2]; // layer1 linear output, fp16 [N,256]
__device__ float g_as1[NN * 4];
__device__ float g_ad1[NN * 4];
__device__ float g_h3[NN * 2];
__device__ float g_as2[NN];
__device__ float g_ad2[NN];
__device__ int   g_cnt[NN];
__device__ int   g_rowptr[NN + 1];
__device__ int   g_cursor[NN];
__device__ int   g_csr[ETOT];             // src node per incoming edge, grouped by dst

__device__ __forceinline__ float lrelu(float x) { return x > 0.f ? x : NEG_SLOPE * x; }
__device__ __forceinline__ float elu1(float x)  { return x > 0.f ? x : expm1f(x); }

// ---------------- CSR construction ------------------------------------------
__global__ void k_init_cnt() {
    int i = blockIdx.x * blockDim.x + threadIdx.x;
    if (i < NN) g_cnt[i] = 1;   // self loop
}

__global__ void k_degree(const int* __restrict__ ei) {
    int i = blockIdx.x * blockDim.x + threadIdx.x;
    if (i < EE) atomicAdd(&g_cnt[ei[EE + i]], 1);
}

// single-block exclusive scan over g_cnt -> g_rowptr / g_cursor
__global__ void k_scan() {
    __shared__ int part[1024];
    int tid = threadIdx.x;
    const int chunk = (NN + 1023) / 1024;
    int start = tid * chunk;
    int end   = min(start + chunk, NN);
    int sum = 0;
    for (int i = start; i < end; i++) sum += g_cnt[i];
    part[tid] = sum;
    __syncthreads();
    for (int off = 1; off < 1024; off <<= 1) {
        int v = 0;
        if (tid >= off) v = part[tid - off];
        __syncthreads();
        if (tid >= off) part[tid] += v;
        __syncthreads();
    }
    int run = (tid == 0) ? 0 : part[tid - 1];
    for (int i = start; i < end; i++) {
        g_rowptr[i] = run;
        g_cursor[i] = run;
        run += g_cnt[i];
    }
    if (tid == 1023) g_rowptr[NN] = part[1023];
}

__global__ void k_scatter(const int* __restrict__ ei) {
    int i = blockIdx.x * blockDim.x + threadIdx.x;
    if (i < EE) {
        int s = ei[i];
        int d = ei[EE + i];
        int p = atomicAdd(&g_cursor[d], 1);
        g_csr[p] = s;
    } else if (i < ETOT) {
        int n = i - EE;
        int p = atomicAdd(&g_cursor[n], 1);
        g_csr[p] = n;   // self loop
    }
}

// ---------------- GEMM1 (single-pass tf32) + fused alpha epilogue -----------
// h1 = x @ W1 (fp16 out). Each block covers 64 cols = one head, so it also
// computes alpha_src/alpha_dst for its 128 rows for that head.
#define GBM 128
#define GBN 64
#define GBK 32
#define ASTRIDE 36
#define BSTRIDE 72

__device__ __forceinline__ uint32_t f2tf32(float f) {
    uint32_t r;
    asm("cvt.rna.tf32.f32 %0, %1;" : "=r"(r) : "f"(f));
    return r;
}
__device__ __forceinline__ void mma_tf32(float* c, uint32_t a0, uint32_t a1,
                                         uint32_t a2, uint32_t a3,
                                         uint32_t b0, uint32_t b1) {
    asm volatile(
        "mma.sync.aligned.m16n8k8.row.col.f32.tf32.tf32.f32 "
        "{%0,%1,%2,%3}, {%4,%5,%6,%7}, {%8,%9}, {%0,%1,%2,%3};"
        : "+f"(c[0]), "+f"(c[1]), "+f"(c[2]), "+f"(c[3])
        : "r"(a0), "r"(a1), "r"(a2), "r"(a3), "r"(b0), "r"(b1));
}

__global__ __launch_bounds__(256) void k_gemm1_tc(const float* __restrict__ A,
                                                  const float* __restrict__ B,
                                                  const float* __restrict__ aS1,
                                                  const float* __restrict__ aD1) {
    __shared__ float As[GBM * ASTRIDE];
    __shared__ float Bs[GBK * BSTRIDE];
    __shared__ float sAS[GBM][5];
    __shared__ float sAD[GBM][5];
    const int tid  = threadIdx.x;
    const int wid  = tid >> 5;
    const int lane = tid & 31;
    const int grp  = lane >> 2;
    const int tig  = lane & 3;
    const int wm   = wid & 1;
    const int wn   = wid >> 1;
    const int m0   = blockIdx.x * GBM;
    const int head = blockIdx.y;          // GBN == 64 == one head
    const int n0   = head * GBN;

    float acc[4][2][4];
    #pragma unroll
    for (int i = 0; i < 4; i++)
        #pragma unroll
        for (int j = 0; j < 2; j++)
            #pragma unroll
            for (int k = 0; k < 4; k++) acc[i][j][k] = 0.f;

    float4 pa[4], pb[2];
    auto loadA = [&](int k0, float4* r) {
        #pragma unroll
        for (int i = 0; i < 4; i++) {
            int f = tid + i * 256;
            int row = f >> 3, c4 = f & 7;
            int gr = m0 + row;
            r[i] = (gr < NN) ? *(const float4*)(A + (size_t)gr * F1 + k0 + 4 * c4)
                             : make_float4(0.f, 0.f, 0.f, 0.f);
        }
    };
    auto loadB = [&](int k0, float4* r) {
        #pragma unroll
        for (int i = 0; i < 2; i++) {
            int f = tid + i * 256;
            int row = f >> 4, c4 = f & 15;
            r[i] = *(const float4*)(B + (size_t)(k0 + row) * F2 + n0 + 4 * c4);
        }
    };

    loadA(0, pa);
    loadB(0, pb);

    for (int k0 = 0; k0 < F1; k0 += GBK) {
        #pragma unroll
        for (int i = 0; i < 4; i++) {
            int f = tid + i * 256;
            int row = f >> 3, c4 = f & 7;
            *(float4*)(As + row * ASTRIDE + 4 * c4) = pa[i];
        }
        #pragma unroll
        for (int i = 0; i < 2; i++) {
            int f = tid + i * 256;
            int row = f >> 4, c4 = f & 15;
            *(float4*)(Bs + row * BSTRIDE + 4 * c4) = pb[i];
        }
        __syncthreads();

        if (k0 + GBK < F1) {
            loadA(k0 + GBK, pa);
            loadB(k0 + GBK, pb);
        }

        #pragma unroll
        for (int ks = 0; ks < GBK / 8; ks++) {
            const int kb = ks * 8;
            uint32_t am[4][4];
            #pragma unroll
            for (int mt = 0; mt < 4; mt++) {
                int r = wm * 64 + mt * 16 + grp;
                am[mt][0] = f2tf32(As[r * ASTRIDE + kb + tig]);
                am[mt][1] = f2tf32(As[(r + 8) * ASTRIDE + kb + tig]);
                am[mt][2] = f2tf32(As[r * ASTRIDE + kb + tig + 4]);
                am[mt][3] = f2tf32(As[(r + 8) * ASTRIDE + kb + tig + 4]);
            }
            uint32_t bm[2][2];
            #pragma unroll
            for (int nt = 0; nt < 2; nt++) {
                int c = wn * 16 + nt * 8 + grp;
                bm[nt][0] = f2tf32(Bs[(kb + tig) * BSTRIDE + c]);
                bm[nt][1] = f2tf32(Bs[(kb + tig + 4) * BSTRIDE + c]);
            }
            #pragma unroll
            for (int mt = 0; mt < 4; mt++)
                #pragma unroll
                for (int nt = 0; nt < 2; nt++)
                    mma_tf32(acc[mt][nt], am[mt][0], am[mt][1], am[mt][2], am[mt][3],
                             bm[nt][0], bm[nt][1]);
        }
        __syncthreads();
    }

    // attention vector values for this lane's columns (within head)
    float asv[2][2], adv[2][2];
    #pragma unroll
    for (int nt = 0; nt < 2; nt++) {
        int c = head * 64 + wn * 16 + nt * 8 + 2 * tig;
        asv[nt][0] = aS1[c];     asv[nt][1] = aS1[c + 1];
        adv[nt][0] = aD1[c];     adv[nt][1] = aD1[c + 1];
    }

    // epilogue: fp16 store + per-row alpha partials
    #pragma unroll
    for (int mt = 0; mt < 4; mt++) {
        int r = m0 + wm * 64 + mt * 16 + grp;
        float sS0 = 0.f, sS8 = 0.f, sD0 = 0.f, sD8 = 0.f;
        #pragma unroll
        for (int nt = 0; nt < 2; nt++) {
            int c = n0 + wn * 16 + nt * 8 + 2 * tig;
            if (r < NN)
                *(__half2*)(g_h1h + (size_t)r * F2 + c) =
                    __floats2half2_rn(acc[mt][nt][0], acc[mt][nt][1]);
            if (r + 8 < NN)
                *(__half2*)(g_h1h + (size_t)(r + 8) * F2 + c) =
                    __floats2half2_rn(acc[mt][nt][2], acc[mt][nt][3]);
            sS0 += acc[mt][nt][0] * asv[nt][0] + acc[mt][nt][1] * asv[nt][1];
            sS8 += acc[mt][nt][2] * asv[nt][0] + acc[mt][nt][3] * asv[nt][1];
            sD0 += acc[mt][nt][0] * adv[nt][0] + acc[mt][nt][1] * adv[nt][1];
            sD8 += acc[mt][nt][2] * adv[nt][0] + acc[mt][nt][3] * adv[nt][1];
        }
        // reduce over the quad (tig 0..3 share the same rows)
        #pragma unroll
        for (int o = 1; o <= 2; o <<= 1) {
            sS0 += __shfl_xor_sync(0xffffffffu, sS0, o);
            sS8 += __shfl_xor_sync(0xffffffffu, sS8, o);
            sD0 += __shfl_xor_sync(0xffffffffu, sD0, o);
            sD8 += __shfl_xor_sync(0xffffffffu, sD8, o);
        }
        if (tig == 0) {
            int rl = wm * 64 + mt * 16 + grp;
            sAS[rl][wn] = sS0;  sAS[rl + 8][wn] = sS8;
            sAD[rl][wn] = sD0;  sAD[rl + 8][wn] = sD8;
        }
    }
    __syncthreads();
    if (tid < GBM) {
        int r = m0 + tid;
        if (r < NN) {
            float aS = sAS[tid][0] + sAS[tid][1] + sAS[tid][2] + sAS[tid][3];
            float aD = sAD[tid][0] + sAD[tid][1] + sAD[tid][2] + sAD[tid][3];
            g_as1[4 * r + head] = aS;
            g_ad1[4 * r + head] = aD;
        }
    }
}

// ---------------- layer-1 softmax+aggregate + layer-2 linear (warp per dst) -
__global__ __launch_bounds__(256) void k_agg1f(const float* __restrict__ b1,
                                               const float* __restrict__ W2,
                                               const float* __restrict__ aS2,
                                               const float* __restrict__ aD2) {
    int n = (blockIdx.x * blockDim.x + threadIdx.x) >> 5;
    int lane = threadIdx.x & 31;
    if (n >= NN) return;
    int beg = g_rowptr[n], end = g_rowptr[n + 1];
    const int head = lane >> 3;
    float ad_h = g_ad1[4 * n + head];

    float acc[8] = {0, 0, 0, 0, 0, 0, 0, 0};
    float ssum = 0.f;
    #pragma unroll 2
    for (int e = beg; e < end; e++) {
        int s = g_csr[e];
        float w = __expf(lrelu(g_as1[4 * s + head] + ad_h));
        uint4 hv = *(const uint4*)(g_h1h + (size_t)s * F2 + 8 * lane);
        const __half2* hp = (const __half2*)&hv;
        ssum += w;
        #pragma unroll
        for (int j = 0; j < 4; j++) {
            float2 f = __half22float2(hp[j]);
            acc[2 * j]     += f.x * w;
            acc[2 * j + 1] += f.y * w;
        }
    }
    float r = 1.f / ssum;

    // h2 features for this lane + layer-2 projection (256 -> 2)
    const int fb = 8 * lane;
    float4 bb0 = *(const float4*)(b1 + fb);
    float4 bb1 = *(const float4*)(b1 + fb + 4);
    float s0 = 0.f, s1 = 0.f;
    #pragma unroll
    for (int j = 0; j < 8; j++) {
        float bj = (j < 4) ? (&bb0.x)[j] : (&bb1.x)[j - 4];
        float h2 = elu1(acc[j] * r + bj);
        float2 w2 = *(const float2*)(W2 + 2 * (fb + j));
        s0 += h2 * w2.x;
        s1 += h2 * w2.y;
    }
    #pragma unroll
    for (int o = 16; o; o >>= 1) {
        s0 += __shfl_xor_sync(0xffffffffu, s0, o);
        s1 += __shfl_xor_sync(0xffffffffu, s1, o);
    }
    if (lane == 0) {
        g_h3[2 * n]     = s0;
        g_h3[2 * n + 1] = s1;
        g_as2[n] = s0 * aS2[0] + s1 * aS2[1];
        g_ad2[n] = s0 * aD2[0] + s1 * aD2[1];
    }
}

// ---------------- layer-2 fused softmax+aggregate (warp per dst, ONE pass) --
__global__ __launch_bounds__(256) void k_agg2f(float* __restrict__ out,
                                               const float* __restrict__ b2) {
    int n = (blockIdx.x * blockDim.x + threadIdx.x) >> 5;
    int lane = threadIdx.x & 31;
    if (n >= NN) return;
    int beg = g_rowptr[n], end = g_rowptr[n + 1];
    float adv = g_ad2[n];

    float s = 0, p0 = 0, p1 = 0;
    for (int e = beg + lane; e < end; e += 32) {
        int sn = g_csr[e];
        float ex = __expf(lrelu(g_as2[sn] + adv));
        float2 h = *(const float2*)(g_h3 + 2 * sn);
        s += ex;
        p0 += ex * h.x;
        p1 += ex * h.y;
    }
    #pragma unroll
    for (int o = 16; o; o >>= 1) {
        s  += __shfl_xor_sync(0xffffffffu, s, o);
        p0 += __shfl_xor_sync(0xffffffffu, p0, o);
        p1 += __shfl_xor_sync(0xffffffffu, p1, o);
    }
    if (lane == 0) {
        float inv = 1.f / s;
        out[2 * n]     = p0 * inv + b2[0];
        out[2 * n + 1] = p1 * inv + b2[1];
    }
}

// ---------------- launch ----------------------------------------------------
extern "C" void kernel_launch(void* const* d_in, const int* in_sizes, int n_in,
                              void* d_out, int out_size) {
    const float* x   = (const float*)d_in[0];
    const int*   ei  = (const int*)  d_in[1];
    const float* W1  = (const float*)d_in[2];
    const float* aS1 = (const float*)d_in[3];
    const float* aD1 = (const float*)d_in[4];
    const float* b1  = (const float*)d_in[5];
    const float* W2  = (const float*)d_in[6];
    const float* aS2 = (const float*)d_in[7];
    const float* aD2 = (const float*)d_in[8];
    const float* b2  = (const float*)d_in[9];
    float* out = (float*)d_out;

    // CSR build (graph identical across both layers)
    k_init_cnt<<<(NN + 255) / 256, 256>>>();
    k_degree<<<(EE + 255) / 256, 256>>>(ei);
    k_scan<<<1, 1024>>>();
    k_scatter<<<(ETOT + 255) / 256, 256>>>(ei);

    // layer 1 GEMM (fp16 output) + fused alpha computation
    k_gemm1_tc<<<dim3((NN + GBM - 1) / GBM, F2 / GBN), 256>>>(x, W1, aS1, aD1);

    // layer-1 aggregate fused with layer-2 linear
    int warpGrid = (NN * 32 + 255) / 256;
    k_agg1f<<<warpGrid, 256>>>(b1, W2, aS2, aD2);

    // layer-2 aggregate
    k_agg2f<<<warpGrid, 256>>>(out, b2);
}